// round 12
// baseline (speedup 1.0000x reference)
#include <cuda_runtime.h>
#include <cuda_bf16.h>
#include <math.h>
#include <stdint.h>

static constexpr int B_ = 16, C_ = 16, P_ = 512, D_ = 256;

// Scratch (device globals; allocation in kernel_launch is forbidden)
__device__ __nv_bfloat16 g_context[(size_t)B_ * C_ * P_ * D_];  // [b,c][p][d]
__device__ __nv_bfloat16 g_qr[(size_t)B_ * C_ * P_ * D_];       // [b,c][p][d]
__device__ __nv_bfloat16 g_q[(size_t)B_ * C_ * P_ * D_];        // [b,c][p][e]
__device__ __nv_bfloat16 g_k[(size_t)B_ * C_ * P_ * D_];        // [b,c][p][e]
__device__ __nv_bfloat16 g_vT[(size_t)B_ * C_ * P_ * D_];       // [b,c][e][p]
__device__ __nv_bfloat16 g_scores[(size_t)B_ * C_ * P_ * P_];   // [b,c][p][q]
__device__ __nv_bfloat16 g_wqT[(size_t)C_ * D_ * D_];           // [c][e][d]
__device__ __nv_bfloat16 g_wkT[(size_t)C_ * D_ * D_];
__device__ __nv_bfloat16 g_wvT[(size_t)C_ * D_ * D_];

// ---------------------------------------------------------------------------
// helpers
// ---------------------------------------------------------------------------
__device__ __forceinline__ uint32_t smem_u32(const void* p) {
    uint32_t a;
    asm("{ .reg .u64 t; cvta.to.shared.u64 t, %1; cvt.u32.u64 %0, t; }"
        : "=r"(a) : "l"(p));
    return a;
}
__device__ __forceinline__ void cpasync16(void* smem, const void* gmem) {
    unsigned s = (unsigned)__cvta_generic_to_shared(smem);
    asm volatile("cp.async.cg.shared.global [%0], [%1], 16;\n" :: "r"(s), "l"(gmem));
}
__device__ __forceinline__ void mma_bf16(float* c, const uint32_t* a, const uint32_t* b) {
    asm volatile(
        "mma.sync.aligned.m16n8k16.row.col.f32.bf16.bf16.f32 "
        "{%0,%1,%2,%3}, {%4,%5,%6,%7}, {%8,%9}, {%0,%1,%2,%3};"
        : "+f"(c[0]), "+f"(c[1]), "+f"(c[2]), "+f"(c[3])
        : "r"(a[0]), "r"(a[1]), "r"(a[2]), "r"(a[3]), "r"(b[0]), "r"(b[1]));
}
__device__ __forceinline__ void ldsm4(uint32_t& r0, uint32_t& r1,
                                      uint32_t& r2, uint32_t& r3, uint32_t addr) {
    asm volatile("ldmatrix.sync.aligned.m8n8.x4.shared.b16 {%0,%1,%2,%3}, [%4];"
                 : "=r"(r0), "=r"(r1), "=r"(r2), "=r"(r3) : "r"(addr));
}
__device__ __forceinline__ uint32_t packbf(float x, float y) {
    __nv_bfloat162 h = __floats2bfloat162_rn(x, y);
    return *(uint32_t*)&h;
}

// ---------------------------------------------------------------------------
// 0) transpose weights to bf16 [c][e][d]
// ---------------------------------------------------------------------------
__global__ void transpose_w_kernel(const float* __restrict__ wq,
                                   const float* __restrict__ wk,
                                   const float* __restrict__ wv)
{
    __shared__ float tile[32][33];
    int which = blockIdx.z / C_;
    int c     = blockIdx.z % C_;
    const float* src = (which == 0) ? wq : (which == 1) ? wk : wv;
    __nv_bfloat16* dst = (which == 0) ? g_wqT : (which == 1) ? g_wkT : g_wvT;
    src += (size_t)c * D_ * D_;
    dst += (size_t)c * D_ * D_;

    int x0 = blockIdx.x * 32;   // d
    int y0 = blockIdx.y * 32;   // e
    int tx = threadIdx.x, ty = threadIdx.y;
    #pragma unroll
    for (int j = 0; j < 4; j++)
        tile[ty + 8 * j][tx] = src[(size_t)(x0 + ty + 8 * j) * D_ + y0 + tx];
    __syncthreads();
    #pragma unroll
    for (int j = 0; j < 4; j++)
        dst[(size_t)(y0 + ty + 8 * j) * D_ + x0 + tx] =
            __float2bfloat16(tile[tx][ty + 8 * j]);
}

// ---------------------------------------------------------------------------
// 1) context = rowsum-over-C(aw*q) - aw*q, bf16 out; also bf16 query copy
// ---------------------------------------------------------------------------
__global__ void context_kernel(const float* __restrict__ query,
                               const float* __restrict__ aw)
{
    int idx = blockIdx.x * blockDim.x + threadIdx.x;   // over B*P*D/2 (pairs)
    if (idx >= B_ * P_ * D_ / 2) return;
    int b  = idx / (P_ * D_ / 2);
    int pd = (idx - b * (P_ * D_ / 2)) * 2;

    const float* qb  = query + (size_t)b * C_ * P_ * D_ + pd;
    const float* awp = aw + pd;

    float q0[C_], q1[C_], a0[C_], a1[C_];
    float s0 = 0.f, s1 = 0.f;
    #pragma unroll
    for (int c = 0; c < C_; c++) {
        float2 q = *(const float2*)(qb + (size_t)c * P_ * D_);
        float2 w = *(const float2*)(awp + (size_t)c * P_ * D_);
        q0[c] = q.x; q1[c] = q.y;
        a0[c] = w.x * q.x; a1[c] = w.y * q.y;
        s0 += a0[c]; s1 += a1[c];
    }
    __nv_bfloat16* ctx = g_context + (size_t)b * C_ * P_ * D_ + pd;
    __nv_bfloat16* qr  = g_qr + (size_t)b * C_ * P_ * D_ + pd;
    #pragma unroll
    for (int c = 0; c < C_; c++) {
        *(uint32_t*)(ctx + (size_t)c * P_ * D_) = packbf(s0 - a0[c], s1 - a1[c]);
        *(uint32_t*)(qr + (size_t)c * P_ * D_)  = packbf(q0[c], q1[c]);
    }
}

// ---------------------------------------------------------------------------
// 2) Unified batched bf16 GEMM: C[z] = A[z%aMod](MxK) * B[z%bMod](NxK)^T
//    All operands bf16 k-major. CTA 128x128, BK=32, 3-stage cp.async,
//    8 warps (2x4), 64x32 warp tile, m16n8k16, ldmatrix.x4.
//    MODE 0: bf16 store. MODE 1: col-bias+relu+scale, bf16. MODE 2: row-bias
//    +relu, bf16. MODE 3: fp32 store.
// ---------------------------------------------------------------------------
template<int K, int MODE>
__global__ __launch_bounds__(256, 2)
void mma_gemm(const __nv_bfloat16* __restrict__ A0,
              const __nv_bfloat16* __restrict__ B0,
              const float* __restrict__ bias0, void* __restrict__ C0,
              int lda, int ldb, int ldc,
              size_t aB, size_t bB, size_t cB,
              int aMod, int bMod, float scale)
{
    constexpr int BK = 32;
    constexpr int SA = 40;                 // bf16 elems per smem row (pad 8)
    constexpr int STG = 128 * SA;          // per operand per stage

    extern __shared__ __nv_bfloat16 sh[];
    __nv_bfloat16* As = sh;                // 3 stages
    __nv_bfloat16* Bs = sh + 3 * STG;

    const int tid  = threadIdx.x;
    const int lane = tid & 31;
    const int warp = tid >> 5;             // 0..7
    const int wm = warp >> 2;              // 0..1  (64 rows)
    const int wn = warp & 3;               // 0..3  (32 cols)
    const int z  = blockIdx.z;
    const int m_blk = blockIdx.x * 128;
    const int n_blk = blockIdx.y * 128;

    const __nv_bfloat16* Ap = A0 + (size_t)(z % aMod) * aB + (size_t)m_blk * lda;
    const __nv_bfloat16* Bp = B0 + (size_t)(z % bMod) * bB + (size_t)n_blk * ldb;

    float acc[4][4][4];
    #pragma unroll
    for (int i = 0; i < 4; i++)
        #pragma unroll
        for (int j = 0; j < 4; j++)
            #pragma unroll
            for (int r = 0; r < 4; r++) acc[i][j][r] = 0.f;

    auto load_tile = [&](int k0, int buf) {
        __nv_bfloat16* Asb = As + buf * STG;
        __nv_bfloat16* Bsb = Bs + buf * STG;
        #pragma unroll
        for (int i = 0; i < 2; i++) {
            int idx = i * 256 + tid;
            int r = idx >> 2, c = (idx & 3) * 8;
            cpasync16(Asb + r * SA + c, Ap + (size_t)r * lda + k0 + c);
            cpasync16(Bsb + r * SA + c, Bp + (size_t)r * ldb + k0 + c);
        }
        asm volatile("cp.async.commit_group;\n");
    };

    constexpr int NT = K / BK;
    load_tile(0, 0);
    load_tile(BK, 1);

    // ldmatrix base addresses (bytes, warp/lane constant)
    const int g  = lane >> 3;              // 0..3 (matrix group)
    const int rw = lane & 7;
    const uint32_t smA = smem_u32(As);
    const uint32_t smB = smem_u32(Bs);
    // A: matrices (r0k0, r8k0, r0k8, r8k8): row = wm*64 + (g&1)*8 + rw, k = (g>>1)*8
    const uint32_t aBase = smA + ((uint32_t)((wm * 64 + (g & 1) * 8 + rw) * SA
                                             + (g >> 1) * 8) << 1);
    // B: matrices (n0k0, n0k8, n8k0, n8k8): n = wn*32 + (g>>1)*8 + rw, k = (g&1)*8
    const uint32_t bBase = smB + ((uint32_t)((wn * 32 + (g >> 1) * 8 + rw) * SA
                                             + (g & 1) * 8) << 1);

    #pragma unroll 1
    for (int t = 0; t < NT; t++) {
        if (t + 2 < NT) {
            load_tile((t + 2) * BK, (t + 2) % 3);
            asm volatile("cp.async.wait_group 2;\n");
        } else if (t + 1 < NT) {
            asm volatile("cp.async.wait_group 1;\n");
        } else {
            asm volatile("cp.async.wait_group 0;\n");
        }
        __syncthreads();

        const uint32_t stOff = (uint32_t)((t % 3) * STG) << 1;
        const uint32_t sA = aBase + stOff;
        const uint32_t sB = bBase + stOff;

        #pragma unroll
        for (int ks = 0; ks < BK; ks += 16) {
            uint32_t afr[4][4];
            #pragma unroll
            for (int i = 0; i < 4; i++)
                ldsm4(afr[i][0], afr[i][1], afr[i][2], afr[i][3],
                      sA + (uint32_t)((i * 16 * SA + ks) << 1));
            uint32_t bfr[4][2];
            #pragma unroll
            for (int j2 = 0; j2 < 2; j2++)
                ldsm4(bfr[2 * j2][0], bfr[2 * j2][1],
                      bfr[2 * j2 + 1][0], bfr[2 * j2 + 1][1],
                      sB + (uint32_t)((j2 * 16 * SA + ks) << 1));
            #pragma unroll
            for (int i = 0; i < 4; i++)
                #pragma unroll
                for (int j = 0; j < 4; j++)
                    mma_bf16(acc[i][j], afr[i], bfr[j]);
        }
        __syncthreads();
    }

    // ----- epilogue -----
    const int biasIdx = (MODE == 2) ? (z % aMod) : (z % bMod);
    #pragma unroll
    for (int j = 0; j < 4; j++) {
        int cidx = n_blk + wn * 32 + j * 8 + 2 * (lane & 3);
        float cb0 = 0.f, cb1 = 0.f;
        if (MODE == 1) {
            const float* bp = bias0 + (size_t)biasIdx * D_ + cidx;
            cb0 = bp[0]; cb1 = bp[1];
        }
        #pragma unroll
        for (int i = 0; i < 4; i++) {
            int r0 = m_blk + wm * 64 + i * 16 + (lane >> 2);
            float v0 = acc[i][j][0], v1 = acc[i][j][1];
            float v2 = acc[i][j][2], v3 = acc[i][j][3];
            if (MODE == 1) {
                v0 = fmaxf(v0 + cb0, 0.f) * scale;
                v1 = fmaxf(v1 + cb1, 0.f) * scale;
                v2 = fmaxf(v2 + cb0, 0.f) * scale;
                v3 = fmaxf(v3 + cb1, 0.f) * scale;
            } else if (MODE == 2) {
                float rb0 = bias0[(size_t)biasIdx * D_ + r0];
                float rb1 = bias0[(size_t)biasIdx * D_ + r0 + 8];
                v0 = fmaxf(v0 + rb0, 0.f);
                v1 = fmaxf(v1 + rb0, 0.f);
                v2 = fmaxf(v2 + rb1, 0.f);
                v3 = fmaxf(v3 + rb1, 0.f);
            }
            if (MODE == 3) {
                float* Cp = (float*)C0 + (size_t)z * cB;
                *(float2*)(Cp + (size_t)r0 * ldc + cidx)       = make_float2(v0, v1);
                *(float2*)(Cp + (size_t)(r0 + 8) * ldc + cidx) = make_float2(v2, v3);
            } else {
                __nv_bfloat16* Cp = (__nv_bfloat16*)C0 + (size_t)z * cB;
                *(uint32_t*)(Cp + (size_t)r0 * ldc + cidx)       = packbf(v0, v1);
                *(uint32_t*)(Cp + (size_t)(r0 + 8) * ldc + cidx) = packbf(v2, v3);
            }
        }
    }
}

// ---------------------------------------------------------------------------
// 3) Softmax over bf16 rows of g_scores (len 512), in place. 1 warp / row.
// ---------------------------------------------------------------------------
__global__ void softmax_kernel()
{
    int gw   = (blockIdx.x * blockDim.x + threadIdx.x) >> 5;
    int lane = threadIdx.x & 31;
    if (gw >= B_ * C_ * P_) return;

    uint4* row = reinterpret_cast<uint4*>(g_scores) + (size_t)gw * (P_ / 8);

    uint4 u[2];
    float f[16];
    float m = -1e30f;
    #pragma unroll
    for (int i = 0; i < 2; i++) {
        u[i] = row[lane + 32 * i];
        const __nv_bfloat16* h = (const __nv_bfloat16*)&u[i];
        #pragma unroll
        for (int j = 0; j < 8; j++) {
            float x = __bfloat162float(h[j]);
            f[i * 8 + j] = x;
            m = fmaxf(m, x);
        }
    }
    #pragma unroll
    for (int o = 16; o > 0; o >>= 1)
        m = fmaxf(m, __shfl_xor_sync(0xffffffffu, m, o));

    float s = 0.f;
    #pragma unroll
    for (int i = 0; i < 16; i++) {
        f[i] = __expf(f[i] - m);
        s += f[i];
    }
    #pragma unroll
    for (int o = 16; o > 0; o >>= 1)
        s += __shfl_xor_sync(0xffffffffu, s, o);

    float inv = 1.0f / s;
    #pragma unroll
    for (int i = 0; i < 2; i++) {
        uint32_t* w = (uint32_t*)&u[i];
        #pragma unroll
        for (int j = 0; j < 4; j++)
            w[j] = packbf(f[i * 8 + j * 2] * inv, f[i * 8 + j * 2 + 1] * inv);
        row[lane + 32 * i] = u[i];
    }
}

// ---------------------------------------------------------------------------
// launch
// ---------------------------------------------------------------------------
extern "C" void kernel_launch(void* const* d_in, const int* in_sizes, int n_in,
                              void* d_out, int out_size)
{
    const float* query = (const float*)d_in[0];
    const float* aw    = (const float*)d_in[1];
    const float* wq    = (const float*)d_in[2];
    const float* wk    = (const float*)d_in[3];
    const float* wv    = (const float*)d_in[4];
    const float* bq    = (const float*)d_in[5];
    const float* bk    = (const float*)d_in[6];
    const float* bv    = (const float*)d_in[7];
    float* out = (float*)d_out;

    __nv_bfloat16 *gctx, *gqr, *gq, *gk, *gvT, *gsc, *gwqT, *gwkT, *gwvT;
    cudaGetSymbolAddress((void**)&gctx, g_context);
    cudaGetSymbolAddress((void**)&gqr, g_qr);
    cudaGetSymbolAddress((void**)&gq, g_q);
    cudaGetSymbolAddress((void**)&gk, g_k);
    cudaGetSymbolAddress((void**)&gvT, g_vT);
    cudaGetSymbolAddress((void**)&gsc, g_scores);
    cudaGetSymbolAddress((void**)&gwqT, g_wqT);
    cudaGetSymbolAddress((void**)&gwkT, g_wkT);
    cudaGetSymbolAddress((void**)&gwvT, g_wvT);

    constexpr int SMEM_BYTES = 6 * 128 * 40 * 2;   // 61440
    cudaFuncSetAttribute(mma_gemm<D_, 1>, cudaFuncAttributeMaxDynamicSharedMemorySize, SMEM_BYTES);
    cudaFuncSetAttribute(mma_gemm<D_, 2>, cudaFuncAttributeMaxDynamicSharedMemorySize, SMEM_BYTES);
    cudaFuncSetAttribute(mma_gemm<D_, 0>, cudaFuncAttributeMaxDynamicSharedMemorySize, SMEM_BYTES);
    cudaFuncSetAttribute(mma_gemm<P_, 3>, cudaFuncAttributeMaxDynamicSharedMemorySize, SMEM_BYTES);

    const float qscale = 1.0f / 16.0f;   // D^-0.5
    const size_t PD = (size_t)P_ * D_;
    const size_t PP = (size_t)P_ * P_;
    const size_t DD = (size_t)D_ * D_;
    const int BC = B_ * C_;

    // 0) transpose weights to bf16 [c][e][d]
    transpose_w_kernel<<<dim3(8, 8, 3 * C_), dim3(32, 8)>>>(wq, wk, wv);

    // 1) context + query (bf16)
    context_kernel<<<(B_ * P_ * D_ / 2 + 255) / 256, 256>>>(query, aw);

    // 2) q-proj: A=qr[z] (512x256), B=wqT[c] (256x256); col-bias+relu+scale
    mma_gemm<D_, 1><<<dim3(4, 2, BC), 256, SMEM_BYTES>>>(gqr, gwqT, bq, gq,
        D_, D_, D_, PD, DD, PD, BC, C_, qscale);
    //    k-proj
    mma_gemm<D_, 1><<<dim3(4, 2, BC), 256, SMEM_BYTES>>>(gctx, gwkT, bk, gk,
        D_, D_, D_, PD, DD, PD, BC, C_, 1.0f);
    //    vT-proj: A=wvT[c] (256x256), B=ctx[z] (512x256) -> vT[e][p]; row-bias+relu
    mma_gemm<D_, 2><<<dim3(2, 4, BC), 256, SMEM_BYTES>>>(gwvT, gctx, bv, gvT,
        D_, D_, P_, DD, PD, PD, C_, BC, 1.0f);

    // 3) scores = q @ k^T : 512x512x256, bf16 out
    mma_gemm<D_, 0><<<dim3(4, 4, BC), 256, SMEM_BYTES>>>(gq, gk, nullptr, gsc,
        D_, D_, P_, PD, PD, PP, BC, BC, 1.0f);

    // 4) softmax in-place on bf16 scores
    softmax_kernel<<<(B_ * C_ * P_) / 8, 256>>>();

    // 5) out = attn @ vT^T : A=attn (512x512), B=vT (256x512), fp32 out
    mma_gemm<P_, 3><<<dim3(4, 2, BC), 256, SMEM_BYTES>>>(gsc, gvT, nullptr, out,
        P_, P_, D_, PP, PD, PD, BC, BC, 1.0f);
}

// round 13
// speedup vs baseline: 1.0925x; 1.0925x over previous
#include <cuda_runtime.h>
#include <cuda_bf16.h>
#include <math.h>
#include <stdint.h>

static constexpr int B_ = 16, C_ = 16, P_ = 512, D_ = 256;

// Scratch (device globals; allocation in kernel_launch is forbidden)
__device__ __nv_bfloat16 g_context[(size_t)B_ * C_ * P_ * D_];  // [b,c][p][d]
__device__ __nv_bfloat16 g_qr[(size_t)B_ * C_ * P_ * D_];       // [b,c][p][d]
__device__ __nv_bfloat16 g_q[(size_t)B_ * C_ * P_ * D_];        // [b,c][p][e]
__device__ __nv_bfloat16 g_k[(size_t)B_ * C_ * P_ * D_];        // [b,c][p][e]
__device__ __nv_bfloat16 g_vT[(size_t)B_ * C_ * P_ * D_];       // [b,c][e][p]
__device__ __nv_bfloat16 g_attn[(size_t)B_ * C_ * P_ * P_];     // [b,c][p][q]
__device__ __nv_bfloat16 g_wqT[(size_t)C_ * D_ * D_];           // [c][e][d]
__device__ __nv_bfloat16 g_wkT[(size_t)C_ * D_ * D_];
__device__ __nv_bfloat16 g_wvT[(size_t)C_ * D_ * D_];

// ---------------------------------------------------------------------------
// helpers
// ---------------------------------------------------------------------------
__device__ __forceinline__ uint32_t smem_u32(const void* p) {
    uint32_t a;
    asm("{ .reg .u64 t; cvta.to.shared.u64 t, %1; cvt.u32.u64 %0, t; }"
        : "=r"(a) : "l"(p));
    return a;
}
__device__ __forceinline__ void cpasync16(void* smem, const void* gmem) {
    unsigned s = (unsigned)__cvta_generic_to_shared(smem);
    asm volatile("cp.async.cg.shared.global [%0], [%1], 16;\n" :: "r"(s), "l"(gmem));
}
__device__ __forceinline__ void mma_bf16(float* c, const uint32_t* a, const uint32_t* b) {
    asm volatile(
        "mma.sync.aligned.m16n8k16.row.col.f32.bf16.bf16.f32 "
        "{%0,%1,%2,%3}, {%4,%5,%6,%7}, {%8,%9}, {%0,%1,%2,%3};"
        : "+f"(c[0]), "+f"(c[1]), "+f"(c[2]), "+f"(c[3])
        : "r"(a[0]), "r"(a[1]), "r"(a[2]), "r"(a[3]), "r"(b[0]), "r"(b[1]));
}
__device__ __forceinline__ void ldsm4(uint32_t& r0, uint32_t& r1,
                                      uint32_t& r2, uint32_t& r3, uint32_t addr) {
    asm volatile("ldmatrix.sync.aligned.m8n8.x4.shared.b16 {%0,%1,%2,%3}, [%4];"
                 : "=r"(r0), "=r"(r1), "=r"(r2), "=r"(r3) : "r"(addr));
}
__device__ __forceinline__ uint32_t packbf(float x, float y) {
    __nv_bfloat162 h = __floats2bfloat162_rn(x, y);
    return *(uint32_t*)&h;
}

// ---------------------------------------------------------------------------
// 0) transpose weights to bf16 [c][e][d]
// ---------------------------------------------------------------------------
__global__ void transpose_w_kernel(const float* __restrict__ wq,
                                   const float* __restrict__ wk,
                                   const float* __restrict__ wv)
{
    __shared__ float tile[32][33];
    int which = blockIdx.z / C_;
    int c     = blockIdx.z % C_;
    const float* src = (which == 0) ? wq : (which == 1) ? wk : wv;
    __nv_bfloat16* dst = (which == 0) ? g_wqT : (which == 1) ? g_wkT : g_wvT;
    src += (size_t)c * D_ * D_;
    dst += (size_t)c * D_ * D_;

    int x0 = blockIdx.x * 32;   // d
    int y0 = blockIdx.y * 32;   // e
    int tx = threadIdx.x, ty = threadIdx.y;
    #pragma unroll
    for (int j = 0; j < 4; j++)
        tile[ty + 8 * j][tx] = src[(size_t)(x0 + ty + 8 * j) * D_ + y0 + tx];
    __syncthreads();
    #pragma unroll
    for (int j = 0; j < 4; j++)
        dst[(size_t)(y0 + ty + 8 * j) * D_ + x0 + tx] =
            __float2bfloat16(tile[tx][ty + 8 * j]);
}

// ---------------------------------------------------------------------------
// 1) context = rowsum-over-C(aw*q) - aw*q, bf16 out; also bf16 query copy
// ---------------------------------------------------------------------------
__global__ void context_kernel(const float* __restrict__ query,
                               const float* __restrict__ aw)
{
    int idx = blockIdx.x * blockDim.x + threadIdx.x;   // over B*P*D/2 (pairs)
    if (idx >= B_ * P_ * D_ / 2) return;
    int b  = idx / (P_ * D_ / 2);
    int pd = (idx - b * (P_ * D_ / 2)) * 2;

    const float* qb  = query + (size_t)b * C_ * P_ * D_ + pd;
    const float* awp = aw + pd;

    float q0[C_], q1[C_], a0[C_], a1[C_];
    float s0 = 0.f, s1 = 0.f;
    #pragma unroll
    for (int c = 0; c < C_; c++) {
        float2 q = *(const float2*)(qb + (size_t)c * P_ * D_);
        float2 w = *(const float2*)(awp + (size_t)c * P_ * D_);
        q0[c] = q.x; q1[c] = q.y;
        a0[c] = w.x * q.x; a1[c] = w.y * q.y;
        s0 += a0[c]; s1 += a1[c];
    }
    __nv_bfloat16* ctx = g_context + (size_t)b * C_ * P_ * D_ + pd;
    __nv_bfloat16* qr  = g_qr + (size_t)b * C_ * P_ * D_ + pd;
    #pragma unroll
    for (int c = 0; c < C_; c++) {
        *(uint32_t*)(ctx + (size_t)c * P_ * D_) = packbf(s0 - a0[c], s1 - a1[c]);
        *(uint32_t*)(qr + (size_t)c * P_ * D_)  = packbf(q0[c], q1[c]);
    }
}

// ---------------------------------------------------------------------------
// 2) Unified batched bf16 GEMM (R7 winner shape): CTA 128x128, 4 warps,
//    64x64 warp tiles; BK=64, 2-stage cp.async; ldmatrix.x4.
//    C[z] = A[z%aMod](MxK) * B[z%bMod](NxK)^T, all bf16 k-major.
//    MODE 1: col-bias+relu+scale, bf16. MODE 2: row-bias+relu, bf16.
//    MODE 3: fp32 store.
// ---------------------------------------------------------------------------
template<int K, int MODE>
__global__ __launch_bounds__(128, 2)
void mma_gemm(const __nv_bfloat16* __restrict__ A0,
              const __nv_bfloat16* __restrict__ B0,
              const float* __restrict__ bias0, void* __restrict__ C0,
              int lda, int ldb, int ldc,
              size_t aB, size_t bB, size_t cB,
              int aMod, int bMod, float scale)
{
    constexpr int BK = 64;
    constexpr int SA = 72;                 // bf16 elems per smem row (pad 8)
    constexpr int STG = 128 * SA;          // per operand per stage

    extern __shared__ __nv_bfloat16 sh[];
    __nv_bfloat16* As = sh;                // 2 stages
    __nv_bfloat16* Bs = sh + 2 * STG;

    const int tid  = threadIdx.x;
    const int lane = tid & 31;
    const int warp = tid >> 5;             // 0..3
    const int wm = warp >> 1;              // 0..1
    const int wn = warp & 1;               // 0..1
    const int z  = blockIdx.z;
    const int m_blk = blockIdx.x * 128;
    const int n_blk = blockIdx.y * 128;

    const __nv_bfloat16* Ap = A0 + (size_t)(z % aMod) * aB + (size_t)m_blk * lda;
    const __nv_bfloat16* Bp = B0 + (size_t)(z % bMod) * bB + (size_t)n_blk * ldb;

    float acc[4][8][4];
    #pragma unroll
    for (int i = 0; i < 4; i++)
        #pragma unroll
        for (int j = 0; j < 8; j++)
            #pragma unroll
            for (int r = 0; r < 4; r++) acc[i][j][r] = 0.f;

    auto load_tile = [&](int k0, int buf) {
        __nv_bfloat16* Asb = As + buf * STG;
        __nv_bfloat16* Bsb = Bs + buf * STG;
        #pragma unroll
        for (int i = 0; i < 8; i++) {
            int idx = i * 128 + tid;
            int r = idx >> 3, c = (idx & 7) * 8;
            cpasync16(Asb + r * SA + c, Ap + (size_t)r * lda + k0 + c);
            cpasync16(Bsb + r * SA + c, Bp + (size_t)r * ldb + k0 + c);
        }
        asm volatile("cp.async.commit_group;\n");
    };

    constexpr int NT = K / BK;
    load_tile(0, 0);

    const int g  = lane >> 3;              // 0..3 (matrix group)
    const int rw = lane & 7;
    const uint32_t smA = smem_u32(As);
    const uint32_t smB = smem_u32(Bs);
    const uint32_t aBase = smA + ((uint32_t)((wm * 64 + (g & 1) * 8 + rw) * SA
                                             + (g >> 1) * 8) << 1);
    const uint32_t bBase = smB + ((uint32_t)((wn * 64 + (g >> 1) * 8 + rw) * SA
                                             + (g & 1) * 8) << 1);

    #pragma unroll 1
    for (int t = 0; t < NT; t++) {
        if (t + 1 < NT) {
            load_tile((t + 1) * BK, (t + 1) & 1);
            asm volatile("cp.async.wait_group 1;\n");
        } else {
            asm volatile("cp.async.wait_group 0;\n");
        }
        __syncthreads();

        const uint32_t stOff = (uint32_t)((t & 1) * STG) << 1;
        const uint32_t sA = aBase + stOff;
        const uint32_t sB = bBase + stOff;

        #pragma unroll
        for (int ks = 0; ks < BK; ks += 16) {
            uint32_t afr[4][4];
            #pragma unroll
            for (int i = 0; i < 4; i++)
                ldsm4(afr[i][0], afr[i][1], afr[i][2], afr[i][3],
                      sA + (uint32_t)((i * 16 * SA + ks) << 1));
            uint32_t bfr[8][2];
            #pragma unroll
            for (int j2 = 0; j2 < 4; j2++)
                ldsm4(bfr[2 * j2][0], bfr[2 * j2][1],
                      bfr[2 * j2 + 1][0], bfr[2 * j2 + 1][1],
                      sB + (uint32_t)((j2 * 16 * SA + ks) << 1));
            #pragma unroll
            for (int i = 0; i < 4; i++)
                #pragma unroll
                for (int j = 0; j < 8; j++)
                    mma_bf16(acc[i][j], afr[i], bfr[j]);
        }
        __syncthreads();
    }

    // ----- epilogue -----
    const int biasIdx = (MODE == 2) ? (z % aMod) : (z % bMod);
    #pragma unroll
    for (int j = 0; j < 8; j++) {
        int cidx = n_blk + wn * 64 + j * 8 + 2 * (lane & 3);
        float cb0 = 0.f, cb1 = 0.f;
        if (MODE == 1) {
            const float* bp = bias0 + (size_t)biasIdx * D_ + cidx;
            cb0 = bp[0]; cb1 = bp[1];
        }
        #pragma unroll
        for (int i = 0; i < 4; i++) {
            int r0 = m_blk + wm * 64 + i * 16 + (lane >> 2);
            float v0 = acc[i][j][0], v1 = acc[i][j][1];
            float v2 = acc[i][j][2], v3 = acc[i][j][3];
            if (MODE == 1) {
                v0 = fmaxf(v0 + cb0, 0.f) * scale;
                v1 = fmaxf(v1 + cb1, 0.f) * scale;
                v2 = fmaxf(v2 + cb0, 0.f) * scale;
                v3 = fmaxf(v3 + cb1, 0.f) * scale;
            } else if (MODE == 2) {
                float rb0 = bias0[(size_t)biasIdx * D_ + r0];
                float rb1 = bias0[(size_t)biasIdx * D_ + r0 + 8];
                v0 = fmaxf(v0 + rb0, 0.f);
                v1 = fmaxf(v1 + rb0, 0.f);
                v2 = fmaxf(v2 + rb1, 0.f);
                v3 = fmaxf(v3 + rb1, 0.f);
            }
            if (MODE == 3) {
                float* Cp = (float*)C0 + (size_t)z * cB;
                *(float2*)(Cp + (size_t)r0 * ldc + cidx)       = make_float2(v0, v1);
                *(float2*)(Cp + (size_t)(r0 + 8) * ldc + cidx) = make_float2(v2, v3);
            } else {
                __nv_bfloat16* Cp = (__nv_bfloat16*)C0 + (size_t)z * cB;
                *(uint32_t*)(Cp + (size_t)r0 * ldc + cidx)       = packbf(v0, v1);
                *(uint32_t*)(Cp + (size_t)(r0 + 8) * ldc + cidx) = packbf(v2, v3);
            }
        }
    }
}

// ---------------------------------------------------------------------------
// 3) Fused scores + softmax: attn[z] = softmax(q[z] @ k[z]^T) (bf16 out).
//    CTA tile M=64 x N=512 (full row), 256 threads = 8 warps, 64x64 warp
//    tiles (warp w owns cols w*64). BK=64, 2-stage. Softmax on fp32 acc.
// ---------------------------------------------------------------------------
static constexpr int FA_SA   = 72;
static constexpr int FA_BSTG = 512 * FA_SA;     // k-operand stage (elems)
static constexpr int FA_ASTG = 64 * FA_SA;      // q-operand stage
static constexpr int FA_B_OFF = 0;
static constexpr int FA_A_OFF = 2 * FA_BSTG * 2;                 // bytes
static constexpr int FA_ST_OFF = FA_A_OFF + 2 * FA_ASTG * 2;     // stats
static constexpr int FA_SMEM = FA_ST_OFF + 64 * 8 * 4;           // 167936

__global__ __launch_bounds__(256, 1)
void fused_attn_kernel(const __nv_bfloat16* __restrict__ Q0,
                       const __nv_bfloat16* __restrict__ K0,
                       __nv_bfloat16* __restrict__ S0)
{
    extern __shared__ char shraw[];
    __nv_bfloat16* Bs = (__nv_bfloat16*)(shraw + FA_B_OFF);
    __nv_bfloat16* As = (__nv_bfloat16*)(shraw + FA_A_OFF);
    float* stats = (float*)(shraw + FA_ST_OFF);   // [64][8]

    const int tid  = threadIdx.x;
    const int lane = tid & 31;
    const int w    = tid >> 5;                    // 0..7 (col group)
    const int z    = blockIdx.y;
    const int m_blk = blockIdx.x * 64;

    const __nv_bfloat16* Ap = Q0 + (size_t)z * (P_ * D_) + (size_t)m_blk * D_;
    const __nv_bfloat16* Bp = K0 + (size_t)z * (P_ * D_);

    float acc[4][8][4];
    #pragma unroll
    for (int i = 0; i < 4; i++)
        #pragma unroll
        for (int j = 0; j < 8; j++)
            #pragma unroll
            for (int r = 0; r < 4; r++) acc[i][j][r] = 0.f;

    auto load_tile = [&](int k0, int buf) {
        __nv_bfloat16* Asb = As + buf * FA_ASTG;
        __nv_bfloat16* Bsb = Bs + buf * FA_BSTG;
        #pragma unroll
        for (int i = 0; i < 2; i++) {              // A: 64 x 64
            int idx = i * 256 + tid;
            int r = idx >> 3, c = (idx & 7) * 8;
            cpasync16(Asb + r * FA_SA + c, Ap + (size_t)r * D_ + k0 + c);
        }
        #pragma unroll
        for (int i = 0; i < 16; i++) {             // B: 512 x 64
            int idx = i * 256 + tid;
            int r = idx >> 3, c = (idx & 7) * 8;
            cpasync16(Bsb + r * FA_SA + c, Bp + (size_t)r * D_ + k0 + c);
        }
        asm volatile("cp.async.commit_group;\n");
    };

    constexpr int NT = D_ / 64;                    // 4
    load_tile(0, 0);

    const int g  = lane >> 3;
    const int rw = lane & 7;
    const uint32_t aBase = smem_u32(As)
        + ((uint32_t)(((g & 1) * 8 + rw) * FA_SA + (g >> 1) * 8) << 1);
    const uint32_t bBase = smem_u32(Bs)
        + ((uint32_t)((w * 64 + (g >> 1) * 8 + rw) * FA_SA + (g & 1) * 8) << 1);

    #pragma unroll 1
    for (int t = 0; t < NT; t++) {
        if (t + 1 < NT) {
            load_tile((t + 1) * 64, (t + 1) & 1);
            asm volatile("cp.async.wait_group 1;\n");
        } else {
            asm volatile("cp.async.wait_group 0;\n");
        }
        __syncthreads();

        const uint32_t sA = aBase + ((uint32_t)((t & 1) * FA_ASTG) << 1);
        const uint32_t sB = bBase + ((uint32_t)((t & 1) * FA_BSTG) << 1);

        #pragma unroll
        for (int ks = 0; ks < 64; ks += 16) {
            uint32_t afr[4][4];
            #pragma unroll
            for (int i = 0; i < 4; i++)
                ldsm4(afr[i][0], afr[i][1], afr[i][2], afr[i][3],
                      sA + (uint32_t)((i * 16 * FA_SA + ks) << 1));
            uint32_t bfr[8][2];
            #pragma unroll
            for (int j2 = 0; j2 < 4; j2++)
                ldsm4(bfr[2 * j2][0], bfr[2 * j2][1],
                      bfr[2 * j2 + 1][0], bfr[2 * j2 + 1][1],
                      sB + (uint32_t)((j2 * 16 * FA_SA + ks) << 1));
            #pragma unroll
            for (int i = 0; i < 4; i++)
                #pragma unroll
                for (int j = 0; j < 8; j++)
                    mma_bf16(acc[i][j], afr[i], bfr[j]);
        }
        __syncthreads();
    }

    // ----- softmax epilogue over full rows (N=512 inside this CTA) -----
    const int q4 = lane >> 2;          // row sub-index 0..7
    // local row max over this warp's 64 cols
    float lm[4][2];
    #pragma unroll
    for (int i = 0; i < 4; i++)
        #pragma unroll
        for (int h = 0; h < 2; h++) {
            float m = -1e30f;
            #pragma unroll
            for (int j = 0; j < 8; j++)
                m = fmaxf(m, fmaxf(acc[i][j][2 * h], acc[i][j][2 * h + 1]));
            m = fmaxf(m, __shfl_xor_sync(0xffffffffu, m, 1));
            m = fmaxf(m, __shfl_xor_sync(0xffffffffu, m, 2));
            lm[i][h] = m;
        }
    if ((lane & 3) == 0) {
        #pragma unroll
        for (int i = 0; i < 4; i++)
            #pragma unroll
            for (int h = 0; h < 2; h++)
                stats[(i * 16 + h * 8 + q4) * 8 + w] = lm[i][h];
    }
    __syncthreads();
    float gm[4][2];
    #pragma unroll
    for (int i = 0; i < 4; i++)
        #pragma unroll
        for (int h = 0; h < 2; h++) {
            const float* sp = stats + (i * 16 + h * 8 + q4) * 8;
            float m = sp[0];
            #pragma unroll
            for (int ww = 1; ww < 8; ww++) m = fmaxf(m, sp[ww]);
            gm[i][h] = m;
        }
    __syncthreads();
    // exp + local sum
    float ls[4][2];
    #pragma unroll
    for (int i = 0; i < 4; i++)
        #pragma unroll
        for (int h = 0; h < 2; h++) {
            float s = 0.f;
            #pragma unroll
            for (int j = 0; j < 8; j++) {
                float e0 = __expf(acc[i][j][2 * h]     - gm[i][h]);
                float e1 = __expf(acc[i][j][2 * h + 1] - gm[i][h]);
                acc[i][j][2 * h]     = e0;
                acc[i][j][2 * h + 1] = e1;
                s += e0 + e1;
            }
            s += __shfl_xor_sync(0xffffffffu, s, 1);
            s += __shfl_xor_sync(0xffffffffu, s, 2);
            ls[i][h] = s;
        }
    if ((lane & 3) == 0) {
        #pragma unroll
        for (int i = 0; i < 4; i++)
            #pragma unroll
            for (int h = 0; h < 2; h++)
                stats[(i * 16 + h * 8 + q4) * 8 + w] = ls[i][h];
    }
    __syncthreads();
    float inv[4][2];
    #pragma unroll
    for (int i = 0; i < 4; i++)
        #pragma unroll
        for (int h = 0; h < 2; h++) {
            const float* sp = stats + (i * 16 + h * 8 + q4) * 8;
            float s = sp[0];
            #pragma unroll
            for (int ww = 1; ww < 8; ww++) s += sp[ww];
            inv[i][h] = 1.0f / s;
        }

    // store normalized attn (bf16)
    __nv_bfloat16* Sp = S0 + (size_t)z * (P_ * P_);
    #pragma unroll
    for (int j = 0; j < 8; j++) {
        int cidx = w * 64 + j * 8 + 2 * (lane & 3);
        #pragma unroll
        for (int i = 0; i < 4; i++) {
            int r0 = m_blk + i * 16 + q4;
            *(uint32_t*)(Sp + (size_t)r0 * P_ + cidx) =
                packbf(acc[i][j][0] * inv[i][0], acc[i][j][1] * inv[i][0]);
            *(uint32_t*)(Sp + (size_t)(r0 + 8) * P_ + cidx) =
                packbf(acc[i][j][2] * inv[i][1], acc[i][j][3] * inv[i][1]);
        }
    }
}

// ---------------------------------------------------------------------------
// launch
// ---------------------------------------------------------------------------
extern "C" void kernel_launch(void* const* d_in, const int* in_sizes, int n_in,
                              void* d_out, int out_size)
{
    const float* query = (const float*)d_in[0];
    const float* aw    = (const float*)d_in[1];
    const float* wq    = (const float*)d_in[2];
    const float* wk    = (const float*)d_in[3];
    const float* wv    = (const float*)d_in[4];
    const float* bq    = (const float*)d_in[5];
    const float* bk    = (const float*)d_in[6];
    const float* bv    = (const float*)d_in[7];
    float* out = (float*)d_out;

    __nv_bfloat16 *gctx, *gqr, *gq, *gk, *gvT, *gat, *gwqT, *gwkT, *gwvT;
    cudaGetSymbolAddress((void**)&gctx, g_context);
    cudaGetSymbolAddress((void**)&gqr, g_qr);
    cudaGetSymbolAddress((void**)&gq, g_q);
    cudaGetSymbolAddress((void**)&gk, g_k);
    cudaGetSymbolAddress((void**)&gvT, g_vT);
    cudaGetSymbolAddress((void**)&gat, g_attn);
    cudaGetSymbolAddress((void**)&gwqT, g_wqT);
    cudaGetSymbolAddress((void**)&gwkT, g_wkT);
    cudaGetSymbolAddress((void**)&gwvT, g_wvT);

    constexpr int SMEM_BYTES = 2 * 2 * 128 * 72 * 2;   // 73728
    cudaFuncSetAttribute(mma_gemm<D_, 1>, cudaFuncAttributeMaxDynamicSharedMemorySize, SMEM_BYTES);
    cudaFuncSetAttribute(mma_gemm<D_, 2>, cudaFuncAttributeMaxDynamicSharedMemorySize, SMEM_BYTES);
    cudaFuncSetAttribute(mma_gemm<P_, 3>, cudaFuncAttributeMaxDynamicSharedMemorySize, SMEM_BYTES);
    cudaFuncSetAttribute(fused_attn_kernel, cudaFuncAttributeMaxDynamicSharedMemorySize, FA_SMEM);

    const float qscale = 1.0f / 16.0f;   // D^-0.5
    const size_t PD = (size_t)P_ * D_;
    const size_t PP = (size_t)P_ * P_;
    const size_t DD = (size_t)D_ * D_;
    const int BC = B_ * C_;

    // 0) transpose weights to bf16 [c][e][d]
    transpose_w_kernel<<<dim3(8, 8, 3 * C_), dim3(32, 8)>>>(wq, wk, wv);

    // 1) context + query (bf16)
    context_kernel<<<(B_ * P_ * D_ / 2 + 255) / 256, 256>>>(query, aw);

    // 2) q-proj: A=qr[z] (512x256), B=wqT[c] (256x256); col-bias+relu+scale
    mma_gemm<D_, 1><<<dim3(4, 2, BC), 128, SMEM_BYTES>>>(gqr, gwqT, bq, gq,
        D_, D_, D_, PD, DD, PD, BC, C_, qscale);
    //    k-proj
    mma_gemm<D_, 1><<<dim3(4, 2, BC), 128, SMEM_BYTES>>>(gctx, gwkT, bk, gk,
        D_, D_, D_, PD, DD, PD, BC, C_, 1.0f);
    //    vT-proj: A=wvT[c] (256x256), B=ctx[z] (512x256) -> vT[e][p]; row-bias+relu
    mma_gemm<D_, 2><<<dim3(2, 4, BC), 128, SMEM_BYTES>>>(gwvT, gctx, bv, gvT,
        D_, D_, P_, DD, PD, PD, C_, BC, 1.0f);

    // 3) fused scores + softmax -> attn (bf16)
    fused_attn_kernel<<<dim3(8, BC), 256, FA_SMEM>>>(gq, gk, gat);

    // 4) out = attn @ vT^T : A=attn (512x512), B=vT (256x512), fp32 out
    mma_gemm<P_, 3><<<dim3(4, 2, BC), 128, SMEM_BYTES>>>(gat, gvT, nullptr, out,
        P_, P_, D_, PP, PD, PD, BC, BC, 1.0f);
}

// round 14
// speedup vs baseline: 1.1408x; 1.0442x over previous
#include <cuda_runtime.h>
#include <cuda_bf16.h>
#include <math.h>
#include <stdint.h>

static constexpr int B_ = 16, C_ = 16, P_ = 512, D_ = 256;

// Scratch (device globals; allocation in kernel_launch is forbidden)
__device__ __nv_bfloat16 g_context[(size_t)B_ * C_ * P_ * D_];  // [b,c][p][d]
__device__ __nv_bfloat16 g_qr[(size_t)B_ * C_ * P_ * D_];       // [b,c][p][d]
__device__ __nv_bfloat16 g_q[(size_t)B_ * C_ * P_ * D_];        // [b,c][p][e]
__device__ __nv_bfloat16 g_k[(size_t)B_ * C_ * P_ * D_];        // [b,c][p][e]
__device__ __nv_bfloat16 g_vT[(size_t)B_ * C_ * P_ * D_];       // [b,c][e][p]
__device__ __nv_bfloat16 g_wqT[(size_t)C_ * D_ * D_];           // [c][e][d]
__device__ __nv_bfloat16 g_wkT[(size_t)C_ * D_ * D_];
__device__ __nv_bfloat16 g_wvT[(size_t)C_ * D_ * D_];

// ---------------------------------------------------------------------------
// helpers
// ---------------------------------------------------------------------------
__device__ __forceinline__ uint32_t smem_u32(const void* p) {
    uint32_t a;
    asm("{ .reg .u64 t; cvta.to.shared.u64 t, %1; cvt.u32.u64 %0, t; }"
        : "=r"(a) : "l"(p));
    return a;
}
__device__ __forceinline__ void cpasync16(void* smem, const void* gmem) {
    unsigned s = (unsigned)__cvta_generic_to_shared(smem);
    asm volatile("cp.async.cg.shared.global [%0], [%1], 16;\n" :: "r"(s), "l"(gmem));
}
__device__ __forceinline__ void mma_bf16(float* c, const uint32_t* a, const uint32_t* b) {
    asm volatile(
        "mma.sync.aligned.m16n8k16.row.col.f32.bf16.bf16.f32 "
        "{%0,%1,%2,%3}, {%4,%5,%6,%7}, {%8,%9}, {%0,%1,%2,%3};"
        : "+f"(c[0]), "+f"(c[1]), "+f"(c[2]), "+f"(c[3])
        : "r"(a[0]), "r"(a[1]), "r"(a[2]), "r"(a[3]), "r"(b[0]), "r"(b[1]));
}
__device__ __forceinline__ void ldsm4(uint32_t& r0, uint32_t& r1,
                                      uint32_t& r2, uint32_t& r3, uint32_t addr) {
    asm volatile("ldmatrix.sync.aligned.m8n8.x4.shared.b16 {%0,%1,%2,%3}, [%4];"
                 : "=r"(r0), "=r"(r1), "=r"(r2), "=r"(r3) : "r"(addr));
}
__device__ __forceinline__ uint32_t packbf(float x, float y) {
    __nv_bfloat162 h = __floats2bfloat162_rn(x, y);
    return *(uint32_t*)&h;
}

// ---------------------------------------------------------------------------
// 0) transpose weights to bf16 [c][e][d]
// ---------------------------------------------------------------------------
__global__ void transpose_w_kernel(const float* __restrict__ wq,
                                   const float* __restrict__ wk,
                                   const float* __restrict__ wv)
{
    __shared__ float tile[32][33];
    int which = blockIdx.z / C_;
    int c     = blockIdx.z % C_;
    const float* src = (which == 0) ? wq : (which == 1) ? wk : wv;
    __nv_bfloat16* dst = (which == 0) ? g_wqT : (which == 1) ? g_wkT : g_wvT;
    src += (size_t)c * D_ * D_;
    dst += (size_t)c * D_ * D_;

    int x0 = blockIdx.x * 32;   // d
    int y0 = blockIdx.y * 32;   // e
    int tx = threadIdx.x, ty = threadIdx.y;
    #pragma unroll
    for (int j = 0; j < 4; j++)
        tile[ty + 8 * j][tx] = src[(size_t)(x0 + ty + 8 * j) * D_ + y0 + tx];
    __syncthreads();
    #pragma unroll
    for (int j = 0; j < 4; j++)
        dst[(size_t)(y0 + ty + 8 * j) * D_ + x0 + tx] =
            __float2bfloat16(tile[tx][ty + 8 * j]);
}

// ---------------------------------------------------------------------------
// 1) context = rowsum-over-C(aw*q) - aw*q, bf16 out; also bf16 query copy
// ---------------------------------------------------------------------------
__global__ void context_kernel(const float* __restrict__ query,
                               const float* __restrict__ aw)
{
    int idx = blockIdx.x * blockDim.x + threadIdx.x;   // over B*P*D/2 (pairs)
    if (idx >= B_ * P_ * D_ / 2) return;
    int b  = idx / (P_ * D_ / 2);
    int pd = (idx - b * (P_ * D_ / 2)) * 2;

    const float* qb  = query + (size_t)b * C_ * P_ * D_ + pd;
    const float* awp = aw + pd;

    float q0[C_], q1[C_], a0[C_], a1[C_];
    float s0 = 0.f, s1 = 0.f;
    #pragma unroll
    for (int c = 0; c < C_; c++) {
        float2 q = *(const float2*)(qb + (size_t)c * P_ * D_);
        float2 w = *(const float2*)(awp + (size_t)c * P_ * D_);
        q0[c] = q.x; q1[c] = q.y;
        a0[c] = w.x * q.x; a1[c] = w.y * q.y;
        s0 += a0[c]; s1 += a1[c];
    }
    __nv_bfloat16* ctx = g_context + (size_t)b * C_ * P_ * D_ + pd;
    __nv_bfloat16* qr  = g_qr + (size_t)b * C_ * P_ * D_ + pd;
    #pragma unroll
    for (int c = 0; c < C_; c++) {
        *(uint32_t*)(ctx + (size_t)c * P_ * D_) = packbf(s0 - a0[c], s1 - a1[c]);
        *(uint32_t*)(qr + (size_t)c * P_ * D_)  = packbf(q0[c], q1[c]);
    }
}

// ---------------------------------------------------------------------------
// 2) Batched bf16 GEMM (projections): CTA 128x128, 4 warps, 64x64 warp
//    tiles; BK=64, 2-stage cp.async; ldmatrix.x4.
//    C[z] = A[z%aMod](MxK) * B[z%bMod](NxK)^T, all bf16 k-major.
//    MODE 1: col-bias+relu+scale. MODE 2: row-bias+relu.
// ---------------------------------------------------------------------------
template<int K, int MODE>
__global__ __launch_bounds__(128, 2)
void mma_gemm(const __nv_bfloat16* __restrict__ A0,
              const __nv_bfloat16* __restrict__ B0,
              const float* __restrict__ bias0, void* __restrict__ C0,
              int lda, int ldb, int ldc,
              size_t aB, size_t bB, size_t cB,
              int aMod, int bMod, float scale)
{
    constexpr int BK = 64;
    constexpr int SA = 72;
    constexpr int STG = 128 * SA;

    extern __shared__ __nv_bfloat16 sh[];
    __nv_bfloat16* As = sh;                // 2 stages
    __nv_bfloat16* Bs = sh + 2 * STG;

    const int tid  = threadIdx.x;
    const int lane = tid & 31;
    const int warp = tid >> 5;
    const int wm = warp >> 1;
    const int wn = warp & 1;
    const int z  = blockIdx.z;
    const int m_blk = blockIdx.x * 128;
    const int n_blk = blockIdx.y * 128;

    const __nv_bfloat16* Ap = A0 + (size_t)(z % aMod) * aB + (size_t)m_blk * lda;
    const __nv_bfloat16* Bp = B0 + (size_t)(z % bMod) * bB + (size_t)n_blk * ldb;

    float acc[4][8][4];
    #pragma unroll
    for (int i = 0; i < 4; i++)
        #pragma unroll
        for (int j = 0; j < 8; j++)
            #pragma unroll
            for (int r = 0; r < 4; r++) acc[i][j][r] = 0.f;

    auto load_tile = [&](int k0, int buf) {
        __nv_bfloat16* Asb = As + buf * STG;
        __nv_bfloat16* Bsb = Bs + buf * STG;
        #pragma unroll
        for (int i = 0; i < 8; i++) {
            int idx = i * 128 + tid;
            int r = idx >> 3, c = (idx & 7) * 8;
            cpasync16(Asb + r * SA + c, Ap + (size_t)r * lda + k0 + c);
            cpasync16(Bsb + r * SA + c, Bp + (size_t)r * ldb + k0 + c);
        }
        asm volatile("cp.async.commit_group;\n");
    };

    constexpr int NT = K / BK;
    load_tile(0, 0);

    const int g  = lane >> 3;
    const int rw = lane & 7;
    const uint32_t smA = smem_u32(As);
    const uint32_t smB = smem_u32(Bs);
    const uint32_t aBase = smA + ((uint32_t)((wm * 64 + (g & 1) * 8 + rw) * SA
                                             + (g >> 1) * 8) << 1);
    const uint32_t bBase = smB + ((uint32_t)((wn * 64 + (g >> 1) * 8 + rw) * SA
                                             + (g & 1) * 8) << 1);

    #pragma unroll 1
    for (int t = 0; t < NT; t++) {
        if (t + 1 < NT) {
            load_tile((t + 1) * BK, (t + 1) & 1);
            asm volatile("cp.async.wait_group 1;\n");
        } else {
            asm volatile("cp.async.wait_group 0;\n");
        }
        __syncthreads();

        const uint32_t stOff = (uint32_t)((t & 1) * STG) << 1;
        const uint32_t sA = aBase + stOff;
        const uint32_t sB = bBase + stOff;

        #pragma unroll
        for (int ks = 0; ks < BK; ks += 16) {
            uint32_t afr[4][4];
            #pragma unroll
            for (int i = 0; i < 4; i++)
                ldsm4(afr[i][0], afr[i][1], afr[i][2], afr[i][3],
                      sA + (uint32_t)((i * 16 * SA + ks) << 1));
            uint32_t bfr[8][2];
            #pragma unroll
            for (int j2 = 0; j2 < 4; j2++)
                ldsm4(bfr[2 * j2][0], bfr[2 * j2][1],
                      bfr[2 * j2 + 1][0], bfr[2 * j2 + 1][1],
                      sB + (uint32_t)((j2 * 16 * SA + ks) << 1));
            #pragma unroll
            for (int i = 0; i < 4; i++)
                #pragma unroll
                for (int j = 0; j < 8; j++)
                    mma_bf16(acc[i][j], afr[i], bfr[j]);
        }
        __syncthreads();
    }

    // ----- epilogue -----
    const int biasIdx = (MODE == 2) ? (z % aMod) : (z % bMod);
    #pragma unroll
    for (int j = 0; j < 8; j++) {
        int cidx = n_blk + wn * 64 + j * 8 + 2 * (lane & 3);
        float cb0 = 0.f, cb1 = 0.f;
        if (MODE == 1) {
            const float* bp = bias0 + (size_t)biasIdx * D_ + cidx;
            cb0 = bp[0]; cb1 = bp[1];
        }
        #pragma unroll
        for (int i = 0; i < 4; i++) {
            int r0 = m_blk + wm * 64 + i * 16 + (lane >> 2);
            float v0 = acc[i][j][0], v1 = acc[i][j][1];
            float v2 = acc[i][j][2], v3 = acc[i][j][3];
            if (MODE == 1) {
                v0 = fmaxf(v0 + cb0, 0.f) * scale;
                v1 = fmaxf(v1 + cb1, 0.f) * scale;
                v2 = fmaxf(v2 + cb0, 0.f) * scale;
                v3 = fmaxf(v3 + cb1, 0.f) * scale;
            } else {
                float rb0 = bias0[(size_t)biasIdx * D_ + r0];
                float rb1 = bias0[(size_t)biasIdx * D_ + r0 + 8];
                v0 = fmaxf(v0 + rb0, 0.f);
                v1 = fmaxf(v1 + rb0, 0.f);
                v2 = fmaxf(v2 + rb1, 0.f);
                v3 = fmaxf(v3 + rb1, 0.f);
            }
            __nv_bfloat16* Cp = (__nv_bfloat16*)C0 + (size_t)z * cB;
            *(uint32_t*)(Cp + (size_t)r0 * ldc + cidx)       = packbf(v0, v1);
            *(uint32_t*)(Cp + (size_t)(r0 + 8) * ldc + cidx) = packbf(v2, v3);
        }
    }
}

// ---------------------------------------------------------------------------
// 3) Fully fused attention: out[64x256] = softmax(q[64xD] @ k^T) @ vT^T.
//    256 threads = 8 warps. Phase 1: scores (warp = 64x64 col slice) +
//    softmax (fp32). attn -> smem bf16. Phase 2: out GEMM, warp = 64x32,
//    K=512 streamed from vT via 2-stage cp.async (aliased smem).
// ---------------------------------------------------------------------------
static constexpr int FL_SA    = 72;
static constexpr int FL_BSTG  = 512 * FL_SA;                 // elems per K-stage
static constexpr int FL_ASTG  = 64 * FL_SA;
static constexpr int FL_A_OFF = 2 * FL_BSTG * 2;             // 147456 B
static constexpr int FL_ST_OFF = FL_A_OFF + 2 * FL_ASTG * 2; // 165888 B
static constexpr int FL_SMEM  = FL_ST_OFF + 64 * 8 * 4;      // 167936 B
// phase-2 aliases (over the phase-1 K-tile region, dead after mainloop)
static constexpr int FL_AT_OFF = 0;            // attn smem 64x520 bf16 = 66560 B
static constexpr int FL_SA2    = 520;
static constexpr int FL_V_OFF  = 66560;        // vT tiles: 2 x 256x72 bf16 = 73728 B
static constexpr int FL_VSTG   = 256 * FL_SA;

__global__ __launch_bounds__(256, 1)
void fused_attn_kernel(const __nv_bfloat16* __restrict__ Q0,
                       const __nv_bfloat16* __restrict__ K0,
                       const __nv_bfloat16* __restrict__ V0,
                       float* __restrict__ O0)
{
    extern __shared__ char shraw[];
    __nv_bfloat16* Bs = (__nv_bfloat16*)(shraw);
    __nv_bfloat16* As = (__nv_bfloat16*)(shraw + FL_A_OFF);
    float* stats = (float*)(shraw + FL_ST_OFF);   // [64][8]
    __nv_bfloat16* attnS = (__nv_bfloat16*)(shraw + FL_AT_OFF);

    const int tid  = threadIdx.x;
    const int lane = tid & 31;
    const int w    = tid >> 5;                    // 0..7
    const int z    = blockIdx.y;
    const int m_blk = blockIdx.x * 64;

    const __nv_bfloat16* Ap = Q0 + (size_t)z * (P_ * D_) + (size_t)m_blk * D_;
    const __nv_bfloat16* Bp = K0 + (size_t)z * (P_ * D_);
    const __nv_bfloat16* Vp = V0 + (size_t)z * (P_ * D_);   // [e][p], 256 x 512

    float acc[4][8][4];
    #pragma unroll
    for (int i = 0; i < 4; i++)
        #pragma unroll
        for (int j = 0; j < 8; j++)
            #pragma unroll
            for (int r = 0; r < 4; r++) acc[i][j][r] = 0.f;

    auto load_tile = [&](int k0, int buf) {
        __nv_bfloat16* Asb = As + buf * FL_ASTG;
        __nv_bfloat16* Bsb = Bs + buf * FL_BSTG;
        #pragma unroll
        for (int i = 0; i < 2; i++) {              // A: 64 x 64
            int idx = i * 256 + tid;
            int r = idx >> 3, c = (idx & 7) * 8;
            cpasync16(Asb + r * FL_SA + c, Ap + (size_t)r * D_ + k0 + c);
        }
        #pragma unroll
        for (int i = 0; i < 16; i++) {             // B: 512 x 64
            int idx = i * 256 + tid;
            int r = idx >> 3, c = (idx & 7) * 8;
            cpasync16(Bsb + r * FL_SA + c, Bp + (size_t)r * D_ + k0 + c);
        }
        asm volatile("cp.async.commit_group;\n");
    };
    auto load_v = [&](int k0, int buf) {           // vT: 256 x 64
        __nv_bfloat16* Vsb = (__nv_bfloat16*)(shraw + FL_V_OFF) + buf * FL_VSTG;
        #pragma unroll
        for (int i = 0; i < 8; i++) {
            int idx = i * 256 + tid;
            int r = idx >> 3, c = (idx & 7) * 8;
            cpasync16(Vsb + r * FL_SA + c, Vp + (size_t)r * P_ + k0 + c);
        }
        asm volatile("cp.async.commit_group;\n");
    };

    constexpr int NT = D_ / 64;                    // 4
    load_tile(0, 0);

    const int g  = lane >> 3;
    const int rw = lane & 7;
    const uint32_t aBase = smem_u32(As)
        + ((uint32_t)(((g & 1) * 8 + rw) * FL_SA + (g >> 1) * 8) << 1);
    const uint32_t bBase = smem_u32(Bs)
        + ((uint32_t)((w * 64 + (g >> 1) * 8 + rw) * FL_SA + (g & 1) * 8) << 1);

    #pragma unroll 1
    for (int t = 0; t < NT; t++) {
        if (t + 1 < NT) {
            load_tile((t + 1) * 64, (t + 1) & 1);
            asm volatile("cp.async.wait_group 1;\n");
        } else {
            asm volatile("cp.async.wait_group 0;\n");
        }
        __syncthreads();

        const uint32_t sA = aBase + ((uint32_t)((t & 1) * FL_ASTG) << 1);
        const uint32_t sB = bBase + ((uint32_t)((t & 1) * FL_BSTG) << 1);

        #pragma unroll
        for (int ks = 0; ks < 64; ks += 16) {
            uint32_t afr[4][4];
            #pragma unroll
            for (int i = 0; i < 4; i++)
                ldsm4(afr[i][0], afr[i][1], afr[i][2], afr[i][3],
                      sA + (uint32_t)((i * 16 * FL_SA + ks) << 1));
            uint32_t bfr[8][2];
            #pragma unroll
            for (int j2 = 0; j2 < 4; j2++)
                ldsm4(bfr[2 * j2][0], bfr[2 * j2][1],
                      bfr[2 * j2 + 1][0], bfr[2 * j2 + 1][1],
                      sB + (uint32_t)((j2 * 16 * FL_SA + ks) << 1));
            #pragma unroll
            for (int i = 0; i < 4; i++)
                #pragma unroll
                for (int j = 0; j < 8; j++)
                    mma_bf16(acc[i][j], afr[i], bfr[j]);
        }
        __syncthreads();
    }

    // prefetch vT stage 0 (overlaps softmax; region aliased over dead Bs)
    load_v(0, 0);

    // ----- softmax over full rows (fp32 accumulators) -----
    const int q4 = lane >> 2;
    float lm[4][2];
    #pragma unroll
    for (int i = 0; i < 4; i++)
        #pragma unroll
        for (int h = 0; h < 2; h++) {
            float m = -1e30f;
            #pragma unroll
            for (int j = 0; j < 8; j++)
                m = fmaxf(m, fmaxf(acc[i][j][2 * h], acc[i][j][2 * h + 1]));
            m = fmaxf(m, __shfl_xor_sync(0xffffffffu, m, 1));
            m = fmaxf(m, __shfl_xor_sync(0xffffffffu, m, 2));
            lm[i][h] = m;
        }
    if ((lane & 3) == 0) {
        #pragma unroll
        for (int i = 0; i < 4; i++)
            #pragma unroll
            for (int h = 0; h < 2; h++)
                stats[(i * 16 + h * 8 + q4) * 8 + w] = lm[i][h];
    }
    __syncthreads();
    float gm[4][2];
    #pragma unroll
    for (int i = 0; i < 4; i++)
        #pragma unroll
        for (int h = 0; h < 2; h++) {
            const float* sp = stats + (i * 16 + h * 8 + q4) * 8;
            float m = sp[0];
            #pragma unroll
            for (int ww = 1; ww < 8; ww++) m = fmaxf(m, sp[ww]);
            gm[i][h] = m;
        }
    __syncthreads();
    float ls[4][2];
    #pragma unroll
    for (int i = 0; i < 4; i++)
        #pragma unroll
        for (int h = 0; h < 2; h++) {
            float s = 0.f;
            #pragma unroll
            for (int j = 0; j < 8; j++) {
                float e0 = __expf(acc[i][j][2 * h]     - gm[i][h]);
                float e1 = __expf(acc[i][j][2 * h + 1] - gm[i][h]);
                acc[i][j][2 * h]     = e0;
                acc[i][j][2 * h + 1] = e1;
                s += e0 + e1;
            }
            s += __shfl_xor_sync(0xffffffffu, s, 1);
            s += __shfl_xor_sync(0xffffffffu, s, 2);
            ls[i][h] = s;
        }
    if ((lane & 3) == 0) {
        #pragma unroll
        for (int i = 0; i < 4; i++)
            #pragma unroll
            for (int h = 0; h < 2; h++)
                stats[(i * 16 + h * 8 + q4) * 8 + w] = ls[i][h];
    }
    __syncthreads();
    float inv[4][2];
    #pragma unroll
    for (int i = 0; i < 4; i++)
        #pragma unroll
        for (int h = 0; h < 2; h++) {
            const float* sp = stats + (i * 16 + h * 8 + q4) * 8;
            float s = sp[0];
            #pragma unroll
            for (int ww = 1; ww < 8; ww++) s += sp[ww];
            inv[i][h] = 1.0f / s;
        }

    // store normalized attn (bf16) to smem [64][520]
    #pragma unroll
    for (int j = 0; j < 8; j++) {
        int cidx = w * 64 + j * 8 + 2 * (lane & 3);
        #pragma unroll
        for (int i = 0; i < 4; i++) {
            int r0 = i * 16 + q4;
            *(uint32_t*)(attnS + (size_t)r0 * FL_SA2 + cidx) =
                packbf(acc[i][j][0] * inv[i][0], acc[i][j][1] * inv[i][0]);
            *(uint32_t*)(attnS + (size_t)(r0 + 8) * FL_SA2 + cidx) =
                packbf(acc[i][j][2] * inv[i][1], acc[i][j][3] * inv[i][1]);
        }
    }

    // ----- phase 2: out[64x256] = attnS(64x512) @ vT(256x512)^T -----
    float acc2[4][4][4];
    #pragma unroll
    for (int i = 0; i < 4; i++)
        #pragma unroll
        for (int j = 0; j < 4; j++)
            #pragma unroll
            for (int r = 0; r < 4; r++) acc2[i][j][r] = 0.f;

    const uint32_t aBase2 = smem_u32(attnS)
        + ((uint32_t)(((g & 1) * 8 + rw) * FL_SA2 + (g >> 1) * 8) << 1);
    const uint32_t bBase2 = smem_u32(shraw + FL_V_OFF)
        + ((uint32_t)((w * 32 + (g >> 1) * 8 + rw) * FL_SA + (g & 1) * 8) << 1);

    #pragma unroll 1
    for (int t2 = 0; t2 < 8; t2++) {
        if (t2 + 1 < 8) {
            load_v((t2 + 1) * 64, (t2 + 1) & 1);
            asm volatile("cp.async.wait_group 1;\n");
        } else {
            asm volatile("cp.async.wait_group 0;\n");
        }
        __syncthreads();

        const uint32_t sB = bBase2 + ((uint32_t)((t2 & 1) * FL_VSTG) << 1);

        #pragma unroll
        for (int ks = 0; ks < 64; ks += 16) {
            uint32_t afr[4][4];
            #pragma unroll
            for (int i = 0; i < 4; i++)
                ldsm4(afr[i][0], afr[i][1], afr[i][2], afr[i][3],
                      aBase2 + (uint32_t)((i * 16 * FL_SA2 + t2 * 64 + ks) << 1));
            uint32_t bfr[4][2];
            #pragma unroll
            for (int j2 = 0; j2 < 2; j2++)
                ldsm4(bfr[2 * j2][0], bfr[2 * j2][1],
                      bfr[2 * j2 + 1][0], bfr[2 * j2 + 1][1],
                      sB + (uint32_t)((j2 * 16 * FL_SA + ks) << 1));
            #pragma unroll
            for (int i = 0; i < 4; i++)
                #pragma unroll
                for (int j = 0; j < 4; j++)
                    mma_bf16(acc2[i][j], afr[i], bfr[j]);
        }
        __syncthreads();
    }

    // out store (fp32)
    float* Op = O0 + (size_t)z * (P_ * D_) + (size_t)m_blk * D_;
    #pragma unroll
    for (int j = 0; j < 4; j++) {
        int cidx = w * 32 + j * 8 + 2 * (lane & 3);
        #pragma unroll
        for (int i = 0; i < 4; i++) {
            int r0 = i * 16 + q4;
            *(float2*)(Op + (size_t)r0 * D_ + cidx) =
                make_float2(acc2[i][j][0], acc2[i][j][1]);
            *(float2*)(Op + (size_t)(r0 + 8) * D_ + cidx) =
                make_float2(acc2[i][j][2], acc2[i][j][3]);
        }
    }
}

// ---------------------------------------------------------------------------
// launch
// ---------------------------------------------------------------------------
extern "C" void kernel_launch(void* const* d_in, const int* in_sizes, int n_in,
                              void* d_out, int out_size)
{
    const float* query = (const float*)d_in[0];
    const float* aw    = (const float*)d_in[1];
    const float* wq    = (const float*)d_in[2];
    const float* wk    = (const float*)d_in[3];
    const float* wv    = (const float*)d_in[4];
    const float* bq    = (const float*)d_in[5];
    const float* bk    = (const float*)d_in[6];
    const float* bv    = (const float*)d_in[7];
    float* out = (float*)d_out;

    __nv_bfloat16 *gctx, *gqr, *gq, *gk, *gvT, *gwqT, *gwkT, *gwvT;
    cudaGetSymbolAddress((void**)&gctx, g_context);
    cudaGetSymbolAddress((void**)&gqr, g_qr);
    cudaGetSymbolAddress((void**)&gq, g_q);
    cudaGetSymbolAddress((void**)&gk, g_k);
    cudaGetSymbolAddress((void**)&gvT, g_vT);
    cudaGetSymbolAddress((void**)&gwqT, g_wqT);
    cudaGetSymbolAddress((void**)&gwkT, g_wkT);
    cudaGetSymbolAddress((void**)&gwvT, g_wvT);

    constexpr int SMEM_BYTES = 2 * 2 * 128 * 72 * 2;   // 73728
    cudaFuncSetAttribute(mma_gemm<D_, 1>, cudaFuncAttributeMaxDynamicSharedMemorySize, SMEM_BYTES);
    cudaFuncSetAttribute(mma_gemm<D_, 2>, cudaFuncAttributeMaxDynamicSharedMemorySize, SMEM_BYTES);
    cudaFuncSetAttribute(fused_attn_kernel, cudaFuncAttributeMaxDynamicSharedMemorySize, FL_SMEM);

    const float qscale = 1.0f / 16.0f;   // D^-0.5
    const size_t PD = (size_t)P_ * D_;
    const size_t DD = (size_t)D_ * D_;
    const int BC = B_ * C_;

    // 0) transpose weights to bf16 [c][e][d]
    transpose_w_kernel<<<dim3(8, 8, 3 * C_), dim3(32, 8)>>>(wq, wk, wv);

    // 1) context + query (bf16)
    context_kernel<<<(B_ * P_ * D_ / 2 + 255) / 256, 256>>>(query, aw);

    // 2) projections
    mma_gemm<D_, 1><<<dim3(4, 2, BC), 128, SMEM_BYTES>>>(gqr, gwqT, bq, gq,
        D_, D_, D_, PD, DD, PD, BC, C_, qscale);
    mma_gemm<D_, 1><<<dim3(4, 2, BC), 128, SMEM_BYTES>>>(gctx, gwkT, bk, gk,
        D_, D_, D_, PD, DD, PD, BC, C_, 1.0f);
    mma_gemm<D_, 2><<<dim3(2, 4, BC), 128, SMEM_BYTES>>>(gwvT, gctx, bv, gvT,
        D_, D_, P_, DD, PD, PD, C_, BC, 1.0f);

    // 3) fully fused attention -> out (fp32)
    fused_attn_kernel<<<dim3(8, BC), 256, FL_SMEM>>>(gq, gk, gvT, out);
}